// round 2
// baseline (speedup 1.0000x reference)
#include <cuda_runtime.h>
#include <cuda_bf16.h>
#include <cstdint>

// ---------------------------------------------------------------------------
// GCN: out = Anorm @ relu(Anorm @ relu(Anorm @ (x W1) + b1) W2 + b2) W3 + b3
// Anorm = D^-1/2 (A_set + I_addedAfter) D^-1/2, set-semantics adjacency,
// diagonal coefficient = 1 + (1 if explicit self-edge present).
// ---------------------------------------------------------------------------

#define NNODES 8192
#define FDIM   512
#define WORDS_PER_ROW 256          // 8192 bits / 32
#define MAXDEG 192                 // Poisson(~64) max over 8192 rows; 192 ultra-safe

// Scratch (allocation-free rule: __device__ globals)
__device__ unsigned int g_bits[NNODES * WORDS_PER_ROW];   // 8 MB bit adjacency
__device__ unsigned int g_self[WORDS_PER_ROW];            // self-edge flags
__device__ float g_dinv[NNODES];
__device__ float g_selfcoef[NNODES];                      // (1+self)*dinv[i]
__device__ int   g_cols[NNODES * MAXDEG];                 // off-diagonal neighbor lists
__device__ int   g_cnt[NNODES];
__device__ int   g_is64;                                  // 1 => edge_index is int64
__device__ float g_buf0[NNODES * FDIM];                   // 16 MB ping
__device__ float g_buf1[NNODES * FDIM];                   // 16 MB pong

// ---------------------------------------------------------------------------
// K0: clear bit matrix, pre-set diagonal bits (the +I), clear self flags
// ---------------------------------------------------------------------------
__global__ void k_clear_bits() {
    int idx = blockIdx.x * blockDim.x + threadIdx.x;   // 0 .. 2M-1
    int row = idx >> 8;
    int w   = idx & 255;
    g_bits[idx] = (w == (row >> 5)) ? (1u << (row & 31)) : 0u;
    if (idx < WORDS_PER_ROW) g_self[idx] = 0u;
    if (idx == 0) g_is64 = 1;
}

// ---------------------------------------------------------------------------
// K0b: dtype detection. Indices are < 8192, so int64 data has ALL odd 32-bit
// words zero. We scan only the first 2E words (safe for int32 too).
// ---------------------------------------------------------------------------
__global__ void k_detect(const int* __restrict__ w, int nwords) {
    int i = blockIdx.x * blockDim.x + threadIdx.x;
    int idx = 2 * i + 1;
    if (idx < nwords && w[idx] != 0) g_is64 = 0;   // plain store: idempotent
}

// ---------------------------------------------------------------------------
// K1: scatter edges (set semantics via atomicOr); track self-edges
// ---------------------------------------------------------------------------
__global__ void k_scatter(const int* __restrict__ w, int E) {
    int i = blockIdx.x * blockDim.x + threadIdx.x;
    if (i >= E) return;
    int a, b;
    if (g_is64) { a = w[2 * i]; b = w[2 * E + 2 * i]; }
    else        { a = w[i];     b = w[E + i]; }
    if ((unsigned)a >= NNODES || (unsigned)b >= NNODES) return;  // safety net
    atomicOr(&g_bits[(size_t)a * WORDS_PER_ROW + (b >> 5)], 1u << (b & 31));
    atomicOr(&g_bits[(size_t)b * WORDS_PER_ROW + (a >> 5)], 1u << (a & 31));
    if (a == b) atomicOr(&g_self[a >> 5], 1u << (a & 31));
}

// ---------------------------------------------------------------------------
// K2: per-row (one warp/row): popcount -> deg, dinv, selfcoef; compact
//     off-diagonal columns into g_cols (diagonal handled separately).
// ---------------------------------------------------------------------------
__global__ void k_build_rows() {
    int warp = (blockIdx.x * blockDim.x + threadIdx.x) >> 5;
    int lane = threadIdx.x & 31;
    if (warp >= NNODES) return;
    int row = warp;

    unsigned int w[8];
    const unsigned int* base = &g_bits[(size_t)row * WORDS_PER_ROW + lane * 8];
#pragma unroll
    for (int t = 0; t < 8; t++) w[t] = base[t];

    // strip the diagonal bit from the neighbor list (handled via selfcoef)
    int dw = row >> 5;            // diag word index 0..255
    if ((dw >> 3) == lane) w[dw & 7] &= ~(1u << (row & 31));

    unsigned int cnt = 0;
#pragma unroll
    for (int t = 0; t < 8; t++) cnt += __popc(w[t]);

    // inclusive warp scan
    unsigned int incl = cnt;
#pragma unroll
    for (int d = 1; d < 32; d <<= 1) {
        unsigned int v = __shfl_up_sync(0xFFFFFFFFu, incl, d);
        if (lane >= d) incl += v;
    }
    unsigned int excl  = incl - cnt;
    unsigned int total = __shfl_sync(0xFFFFFFFFu, incl, 31);

    int* cols = &g_cols[(size_t)row * MAXDEG];
    unsigned int o = excl;
#pragma unroll
    for (int t = 0; t < 8; t++) {
        unsigned int bits = w[t];
        int colbase = (lane * 8 + t) * 32;
        while (bits) {
            int b = __ffs(bits) - 1;
            bits &= bits - 1;
            if (o < MAXDEG) cols[o] = colbase + b;
            o++;
        }
    }

    if (lane == 0) {
        int self = (g_self[row >> 5] >> (row & 31)) & 1;
        float deg = (float)total + 1.0f + (float)self;   // offdiag + I + self-edge
        float di = rsqrtf(deg);
        g_dinv[row] = di;
        g_selfcoef[row] = (1.0f + (float)self) * di;
        g_cnt[row] = (int)(total < MAXDEG ? total : MAXDEG);
    }
}

// ---------------------------------------------------------------------------
// K3: dense GEMM  C[8192 x Ncol] = A[8192 x 512] @ B[512 x Ncol], fp32
//     BM=128 BN=64 BK=16, 256 threads, 8x4 micro-tile
// ---------------------------------------------------------------------------
#define BM 128
#define BN 64
#define BK 16
#define APAD 132

__global__ __launch_bounds__(256) void k_gemm(const float* __restrict__ A,
                                              const float* __restrict__ B,
                                              float* __restrict__ C, int Ncol) {
    __shared__ float As[BK][APAD];   // transposed A tile (k-major)
    __shared__ float Bs[BK][BN];

    int tid = threadIdx.x;
    int m0 = blockIdx.y * BM;
    int n0 = blockIdx.x * BN;
    int tx = tid & 15;          // 0..15 -> 4 cols each
    int ty = tid >> 4;          // 0..15 -> 8 rows each

    // load mapping
    int lr = tid >> 2;          // 0..63 (A row within tile)
    int lk = (tid & 3) * 4;     // 0,4,8,12
    int bk = tid >> 4;          // 0..15 (B k-row)
    int bn = (tid & 15) * 4;

    const float* Aptr = A + (size_t)(m0 + lr) * FDIM + lk;
    const float* Bptr = B + (size_t)bk * Ncol + n0 + bn;

    float acc[8][4];
#pragma unroll
    for (int i = 0; i < 8; i++)
#pragma unroll
        for (int j = 0; j < 4; j++) acc[i][j] = 0.0f;

    for (int k0 = 0; k0 < FDIM; k0 += BK) {
        float4 a0 = *(const float4*)(Aptr);
        float4 a1 = *(const float4*)(Aptr + (size_t)64 * FDIM);
        float4 b0 = *(const float4*)(Bptr);
        __syncthreads();
        As[lk + 0][lr] = a0.x; As[lk + 1][lr] = a0.y;
        As[lk + 2][lr] = a0.z; As[lk + 3][lr] = a0.w;
        As[lk + 0][lr + 64] = a1.x; As[lk + 1][lr + 64] = a1.y;
        As[lk + 2][lr + 64] = a1.z; As[lk + 3][lr + 64] = a1.w;
        *(float4*)&Bs[bk][bn] = b0;
        __syncthreads();
#pragma unroll
        for (int kk = 0; kk < BK; kk++) {
            float4 alo = *(const float4*)&As[kk][ty * 8];
            float4 ahi = *(const float4*)&As[kk][ty * 8 + 4];
            float4 b   = *(const float4*)&Bs[kk][tx * 4];
            float av[8] = {alo.x, alo.y, alo.z, alo.w, ahi.x, ahi.y, ahi.z, ahi.w};
#pragma unroll
            for (int i = 0; i < 8; i++) {
                acc[i][0] += av[i] * b.x;
                acc[i][1] += av[i] * b.y;
                acc[i][2] += av[i] * b.z;
                acc[i][3] += av[i] * b.w;
            }
        }
        Aptr += BK;
        Bptr += (size_t)BK * Ncol;
    }

#pragma unroll
    for (int i = 0; i < 8; i++) {
        float4 r = make_float4(acc[i][0], acc[i][1], acc[i][2], acc[i][3]);
        *(float4*)&C[(size_t)(m0 + ty * 8 + i) * Ncol + n0 + tx * 4] = r;
    }
}

// ---------------------------------------------------------------------------
// K4: SpMM  out[row] = (RELU?)( dinv[row] * (selfcoef[row]*tmp[row]
//                      + sum_j dinv[j]*tmp[j]) + bias )
//     one block per row, NCOL/4 threads, float4 per thread
// ---------------------------------------------------------------------------
__device__ __forceinline__ void fma4(float4& a, float w, const float4& v) {
    a.x += w * v.x; a.y += w * v.y; a.z += w * v.z; a.w += w * v.w;
}

template <int NCOL, bool RELU>
__global__ __launch_bounds__(NCOL / 4) void k_spmm(const float* __restrict__ tmp,
                                                   const float* __restrict__ bias,
                                                   float* __restrict__ out) {
    constexpr int T = NCOL / 4;
    int row = blockIdx.x;
    int tid = threadIdx.x;

    __shared__ int   s_cols[MAXDEG];
    __shared__ float s_w[MAXDEG];

    int n = g_cnt[row];
    for (int t = tid; t < n; t += T) {
        int j = g_cols[(size_t)row * MAXDEG + t];
        s_cols[t] = j;
        s_w[t] = g_dinv[j];
    }
    __syncthreads();

    const float4* tp = (const float4*)tmp;
    float4 acc = tp[(size_t)row * T + tid];
    float sc = g_selfcoef[row];
    acc.x *= sc; acc.y *= sc; acc.z *= sc; acc.w *= sc;

    int t = 0;
    for (; t + 4 <= n; t += 4) {
        int j0 = s_cols[t], j1 = s_cols[t + 1], j2 = s_cols[t + 2], j3 = s_cols[t + 3];
        float w0 = s_w[t], w1 = s_w[t + 1], w2 = s_w[t + 2], w3 = s_w[t + 3];
        float4 v0 = tp[(size_t)j0 * T + tid];
        float4 v1 = tp[(size_t)j1 * T + tid];
        float4 v2 = tp[(size_t)j2 * T + tid];
        float4 v3 = tp[(size_t)j3 * T + tid];
        fma4(acc, w0, v0); fma4(acc, w1, v1); fma4(acc, w2, v2); fma4(acc, w3, v3);
    }
    for (; t < n; t++) {
        float4 v = tp[(size_t)s_cols[t] * T + tid];
        fma4(acc, s_w[t], v);
    }

    float di = g_dinv[row];
    const float4* bp = (const float4*)bias;
    float4 bv = bp[tid];
    float4 r;
    r.x = di * acc.x + bv.x;
    r.y = di * acc.y + bv.y;
    r.z = di * acc.z + bv.z;
    r.w = di * acc.w + bv.w;
    if (RELU) {
        r.x = fmaxf(r.x, 0.0f); r.y = fmaxf(r.y, 0.0f);
        r.z = fmaxf(r.z, 0.0f); r.w = fmaxf(r.w, 0.0f);
    }
    ((float4*)out)[(size_t)row * T + tid] = r;
}

// ---------------------------------------------------------------------------
extern "C" void kernel_launch(void* const* d_in, const int* in_sizes, int n_in,
                              void* d_out, int out_size) {
    const float* x  = (const float*)d_in[0];
    const int*   ei = (const int*)d_in[1];     // int32 OR int64 (detected on device)
    const float* W1 = (const float*)d_in[2];
    const float* b1 = (const float*)d_in[3];
    const float* W2 = (const float*)d_in[4];
    const float* b2 = (const float*)d_in[5];
    const float* W3 = (const float*)d_in[6];
    const float* b3 = (const float*)d_in[7];
    float* out = (float*)d_out;

    int E = in_sizes[1] / 2;        // element count is 2E under either dtype

    void *p0 = nullptr, *p1 = nullptr;
    cudaGetSymbolAddress(&p0, g_buf0);
    cudaGetSymbolAddress(&p1, g_buf1);
    float* buf0 = (float*)p0;
    float* buf1 = (float*)p1;

    // --- build normalized adjacency structure ---
    {
        int total = NNODES * WORDS_PER_ROW;
        k_clear_bits<<<total / 256, 256>>>();
        k_detect<<<(E + 255) / 256, 256>>>(ei, 2 * E);   // scans odd words < 2E: safe for both dtypes
        k_scatter<<<(E + 255) / 256, 256>>>(ei, E);
        k_build_rows<<<NNODES / 8, 256>>>();   // 8 warps/block, one warp per row
    }

    dim3 g512(512 / BN, NNODES / BM);
    dim3 g256(256 / BN, NNODES / BM);

    // layer 1: buf0 = x @ W1 ; buf1 = relu(Anorm buf0 + b1)
    k_gemm<<<g512, 256>>>(x, W1, buf0, 512);
    k_spmm<512, true><<<NNODES, 128>>>(buf0, b1, buf1);

    // layer 2
    k_gemm<<<g512, 256>>>(buf1, W2, buf0, 512);
    k_spmm<512, true><<<NNODES, 128>>>(buf0, b2, buf1);

    // layer 3 (256 cols, no relu) -> d_out
    k_gemm<<<g256, 256>>>(buf1, W3, buf0, 256);
    k_spmm<256, false><<<NNODES, 64>>>(buf0, b3, out);
}

// round 4
// speedup vs baseline: 1.2389x; 1.2389x over previous
#include <cuda_runtime.h>
#include <cuda_bf16.h>
#include <cstdint>

// ===========================================================================
// GCN: out = Anorm @ relu(Anorm @ relu(Anorm @ (x W1) + b1) W2 + b2) W3 + b3
// GEMMs: bf16 mma.sync (HMMA) with 3-term split => fp32-accurate.
// SpMM gather in fp32 (L2-bound, at LTS cap).
// ===========================================================================

#define NNODES 8192
#define FDIM   512
#define KTOT   1536                 // [Ah | Ah | Al] x [Bh | Bl | Bh]
#define WORDS_PER_ROW 256
#define MAXDEG 192

__device__ unsigned int g_bits[NNODES * WORDS_PER_ROW];   // 8 MB
__device__ unsigned int g_self[WORDS_PER_ROW];
__device__ float g_dinv[NNODES];
__device__ float g_selfcoef[NNODES];
__device__ int   g_cols[NNODES * MAXDEG];
__device__ int   g_cnt[NNODES];
__device__ int   g_is64;
__device__ float g_buf0[NNODES * FDIM];                   // 16 MB
__device__ float g_buf1[NNODES * FDIM];                   // 16 MB
__device__ __nv_bfloat16 g_abf[NNODES * KTOT];            // 24 MB
__device__ __nv_bfloat16 g_bbf[512 * KTOT];               // 1.5 MB

// ===========================================================================
// Graph build
// ===========================================================================
__global__ void k_clear_bits() {
    int idx = blockIdx.x * blockDim.x + threadIdx.x;
    int row = idx >> 8;
    int w   = idx & 255;
    g_bits[idx] = (w == (row >> 5)) ? (1u << (row & 31)) : 0u;
    if (idx < WORDS_PER_ROW) g_self[idx] = 0u;
    if (idx == 0) g_is64 = 1;
}

__global__ void k_detect(const int* __restrict__ w, int nwords) {
    int i = blockIdx.x * blockDim.x + threadIdx.x;
    int idx = 2 * i + 1;
    if (idx < nwords && w[idx] != 0) g_is64 = 0;
}

__global__ void k_scatter(const int* __restrict__ w, int E) {
    int i = blockIdx.x * blockDim.x + threadIdx.x;
    if (i >= E) return;
    int a, b;
    if (g_is64) { a = w[2 * i]; b = w[2 * E + 2 * i]; }
    else        { a = w[i];     b = w[E + i]; }
    if ((unsigned)a >= NNODES || (unsigned)b >= NNODES) return;
    atomicOr(&g_bits[(size_t)a * WORDS_PER_ROW + (b >> 5)], 1u << (b & 31));
    atomicOr(&g_bits[(size_t)b * WORDS_PER_ROW + (a >> 5)], 1u << (a & 31));
    if (a == b) atomicOr(&g_self[a >> 5], 1u << (a & 31));
}

__global__ void k_build_rows() {
    int warp = (blockIdx.x * blockDim.x + threadIdx.x) >> 5;
    int lane = threadIdx.x & 31;
    if (warp >= NNODES) return;
    int row = warp;

    unsigned int w[8];
    const unsigned int* base = &g_bits[(size_t)row * WORDS_PER_ROW + lane * 8];
#pragma unroll
    for (int t = 0; t < 8; t++) w[t] = base[t];

    int dw = row >> 5;
    if ((dw >> 3) == lane) w[dw & 7] &= ~(1u << (row & 31));

    unsigned int cnt = 0;
#pragma unroll
    for (int t = 0; t < 8; t++) cnt += __popc(w[t]);

    unsigned int incl = cnt;
#pragma unroll
    for (int d = 1; d < 32; d <<= 1) {
        unsigned int v = __shfl_up_sync(0xFFFFFFFFu, incl, d);
        if (lane >= d) incl += v;
    }
    unsigned int excl  = incl - cnt;
    unsigned int total = __shfl_sync(0xFFFFFFFFu, incl, 31);

    int* cols = &g_cols[(size_t)row * MAXDEG];
    unsigned int o = excl;
#pragma unroll
    for (int t = 0; t < 8; t++) {
        unsigned int bits = w[t];
        int colbase = (lane * 8 + t) * 32;
        while (bits) {
            int b = __ffs(bits) - 1;
            bits &= bits - 1;
            if (o < MAXDEG) cols[o] = colbase + b;
            o++;
        }
    }

    if (lane == 0) {
        int self = (g_self[row >> 5] >> (row & 31)) & 1;
        float deg = (float)total + 1.0f + (float)self;
        float di = rsqrtf(deg);
        g_dinv[row] = di;
        g_selfcoef[row] = (1.0f + (float)self) * di;
        g_cnt[row] = (int)(total < MAXDEG ? total : MAXDEG);
    }
}

// ===========================================================================
// Split-precision expansion
// ===========================================================================
__global__ void k_expandA(const float* __restrict__ A, __nv_bfloat16* __restrict__ out) {
    int idx = blockIdx.x * blockDim.x + threadIdx.x;
    int row = idx >> 9;
    int k   = idx & 511;
    float a = A[idx];
    __nv_bfloat16 ah = __float2bfloat16_rn(a);
    __nv_bfloat16 al = __float2bfloat16_rn(a - __bfloat162float(ah));
    size_t b = (size_t)row * KTOT + k;
    out[b] = ah;
    out[b + 512] = ah;
    out[b + 1024] = al;
}

__global__ void k_expandB(const float* __restrict__ W, __nv_bfloat16* __restrict__ out, int Ncol) {
    int idx = blockIdx.x * blockDim.x + threadIdx.x;
    if (idx >= Ncol * 512) return;
    int n = idx >> 9;
    int k = idx & 511;
    float v = W[(size_t)k * Ncol + n];
    __nv_bfloat16 bh = __float2bfloat16_rn(v);
    __nv_bfloat16 bl = __float2bfloat16_rn(v - __bfloat162float(bh));
    size_t b = (size_t)n * KTOT + k;
    out[b] = bh;
    out[b + 512] = bl;
    out[b + 1024] = bh;
}

// ===========================================================================
// bf16 mma.sync GEMM: C[8192 x Ncol] = A'[8192 x 1536] @ (B'^T[Ncol x 1536])^T
// CTA tile 128x128, warp tile 64x32 (8 warps 2x4), BK=32, cp.async dbl-buffer.
// SMEM rows padded to 40 bf16 (80 B) => conflict-free fragment LDS.
// ===========================================================================
#define GPAD 40
#define GNIT (KTOT / 32)            // 48

__device__ __forceinline__ void cp16(uint32_t saddr, const void* g) {
    asm volatile("cp.async.cg.shared.global [%0], [%1], 16;" :: "r"(saddr), "l"(g));
}
__device__ __forceinline__ void cp_commit() { asm volatile("cp.async.commit_group;"); }
template <int N> __device__ __forceinline__ void cp_wait() {
    asm volatile("cp.async.wait_group %0;" :: "n"(N));
}

__device__ __forceinline__ void mma16816(float* c, uint32_t a0, uint32_t a1,
                                         uint32_t a2, uint32_t a3,
                                         uint32_t b0, uint32_t b1) {
    asm volatile(
        "mma.sync.aligned.m16n8k16.row.col.f32.bf16.bf16.f32 "
        "{%0,%1,%2,%3}, {%4,%5,%6,%7}, {%8,%9}, {%0,%1,%2,%3};"
        : "+f"(c[0]), "+f"(c[1]), "+f"(c[2]), "+f"(c[3])
        : "r"(a0), "r"(a1), "r"(a2), "r"(a3), "r"(b0), "r"(b1));
}

__global__ __launch_bounds__(256) void k_gemm_mma(const __nv_bfloat16* __restrict__ Aexp,
                                                  const __nv_bfloat16* __restrict__ Bexp,
                                                  float* __restrict__ C, int Ncol) {
    __shared__ __nv_bfloat16 sA[2][128 * GPAD];
    __shared__ __nv_bfloat16 sB[2][128 * GPAD];

    int tid  = threadIdx.x;
    int wid  = tid >> 5;
    int lane = tid & 31;
    int g    = lane >> 2;        // group id 0..7
    int tig  = lane & 3;         // thread in group

    int m0 = blockIdx.y * 128;
    int n0 = blockIdx.x * 128;
    int wm = (wid >> 2) * 64;    // warp m offset
    int wn = (wid & 3) * 32;     // warp n offset

    const __nv_bfloat16* Ab = Aexp + (size_t)m0 * KTOT;
    const __nv_bfloat16* Bb = Bexp + (size_t)n0 * KTOT;

    // load mapping: 2 chunks of 16B per tile per thread
    int c0i = tid;               // chunk ids tid, tid+256 (512 chunks of 16B = 8KB)
    int r0 = c0i >> 2, s0 = (c0i & 3) * 8;
    int c1i = tid + 256;
    int r1 = c1i >> 2, s1 = (c1i & 3) * 8;

    uint32_t sA0 = (uint32_t)__cvta_generic_to_shared(&sA[0][0]);
    uint32_t sB0 = (uint32_t)__cvta_generic_to_shared(&sB[0][0]);
    const uint32_t bufstride = 128 * GPAD * 2;   // bytes

    float acc[4][4][4];
#pragma unroll
    for (int mt = 0; mt < 4; mt++)
#pragma unroll
        for (int nt = 0; nt < 4; nt++)
#pragma unroll
            for (int j = 0; j < 4; j++) acc[mt][nt][j] = 0.0f;

    // prologue: tile 0 -> buffer 0
    {
        cp16(sA0 + (uint32_t)(r0 * GPAD + s0) * 2, Ab + (size_t)r0 * KTOT + s0);
        cp16(sA0 + (uint32_t)(r1 * GPAD + s1) * 2, Ab + (size_t)r1 * KTOT + s1);
        cp16(sB0 + (uint32_t)(r0 * GPAD + s0) * 2, Bb + (size_t)r0 * KTOT + s0);
        cp16(sB0 + (uint32_t)(r1 * GPAD + s1) * 2, Bb + (size_t)r1 * KTOT + s1);
        cp_commit();
    }

    for (int it = 0; it < GNIT; it++) {
        int b = it & 1;
        if (it + 1 < GNIT) {
            int nb = (it + 1) & 1;
            int k0 = (it + 1) * 32;
            uint32_t sa = sA0 + nb * bufstride;
            uint32_t sbm = sB0 + nb * bufstride;
            cp16(sa  + (uint32_t)(r0 * GPAD + s0) * 2, Ab + (size_t)r0 * KTOT + k0 + s0);
            cp16(sa  + (uint32_t)(r1 * GPAD + s1) * 2, Ab + (size_t)r1 * KTOT + k0 + s1);
            cp16(sbm + (uint32_t)(r0 * GPAD + s0) * 2, Bb + (size_t)r0 * KTOT + k0 + s0);
            cp16(sbm + (uint32_t)(r1 * GPAD + s1) * 2, Bb + (size_t)r1 * KTOT + k0 + s1);
            cp_commit();
            cp_wait<1>();
        } else {
            cp_wait<0>();
        }
        __syncthreads();

        const __nv_bfloat16* At = sA[b];
        const __nv_bfloat16* Bt = sB[b];
#pragma unroll
        for (int ks = 0; ks < 32; ks += 16) {
            int kk = ks + tig * 2;
            // B fragments for 4 n-tiles
            uint32_t bf[4][2];
#pragma unroll
            for (int nt = 0; nt < 4; nt++) {
                int n = wn + nt * 8 + g;
                bf[nt][0] = *(const uint32_t*)&Bt[n * GPAD + kk];
                bf[nt][1] = *(const uint32_t*)&Bt[n * GPAD + kk + 8];
            }
#pragma unroll
            for (int mt = 0; mt < 4; mt++) {
                int m = wm + mt * 16 + g;
                uint32_t a0 = *(const uint32_t*)&At[m * GPAD + kk];
                uint32_t a1 = *(const uint32_t*)&At[(m + 8) * GPAD + kk];
                uint32_t a2 = *(const uint32_t*)&At[m * GPAD + kk + 8];
                uint32_t a3 = *(const uint32_t*)&At[(m + 8) * GPAD + kk + 8];
#pragma unroll
                for (int nt = 0; nt < 4; nt++)
                    mma16816(acc[mt][nt], a0, a1, a2, a3, bf[nt][0], bf[nt][1]);
            }
        }
        __syncthreads();
    }

    // epilogue
#pragma unroll
    for (int mt = 0; mt < 4; mt++) {
        int row = m0 + wm + mt * 16 + g;
#pragma unroll
        for (int nt = 0; nt < 4; nt++) {
            int col = n0 + wn + nt * 8 + tig * 2;
            float2 v0 = make_float2(acc[mt][nt][0], acc[mt][nt][1]);
            float2 v1 = make_float2(acc[mt][nt][2], acc[mt][nt][3]);
            *(float2*)&C[(size_t)row * Ncol + col] = v0;
            *(float2*)&C[(size_t)(row + 8) * Ncol + col] = v1;
        }
    }
}

// ===========================================================================
// SpMM
// ===========================================================================
__device__ __forceinline__ void fma4(float4& a, float w, const float4& v) {
    a.x += w * v.x; a.y += w * v.y; a.z += w * v.z; a.w += w * v.w;
}

template <int NCOL, bool RELU>
__global__ __launch_bounds__(NCOL / 4) void k_spmm(const float* __restrict__ tmp,
                                                   const float* __restrict__ bias,
                                                   float* __restrict__ out) {
    constexpr int T = NCOL / 4;
    int row = blockIdx.x;
    int tid = threadIdx.x;

    __shared__ int   s_cols[MAXDEG];
    __shared__ float s_w[MAXDEG];

    int n = g_cnt[row];
    for (int t = tid; t < n; t += T) {
        int j = g_cols[(size_t)row * MAXDEG + t];
        s_cols[t] = j;
        s_w[t] = g_dinv[j];
    }
    __syncthreads();

    const float4* tp = (const float4*)tmp;
    float4 acc = tp[(size_t)row * T + tid];
    float sc = g_selfcoef[row];
    acc.x *= sc; acc.y *= sc; acc.z *= sc; acc.w *= sc;

    int t = 0;
    for (; t + 4 <= n; t += 4) {
        int j0 = s_cols[t], j1 = s_cols[t + 1], j2 = s_cols[t + 2], j3 = s_cols[t + 3];
        float w0 = s_w[t], w1 = s_w[t + 1], w2 = s_w[t + 2], w3 = s_w[t + 3];
        float4 v0 = tp[(size_t)j0 * T + tid];
        float4 v1 = tp[(size_t)j1 * T + tid];
        float4 v2 = tp[(size_t)j2 * T + tid];
        float4 v3 = tp[(size_t)j3 * T + tid];
        fma4(acc, w0, v0); fma4(acc, w1, v1); fma4(acc, w2, v2); fma4(acc, w3, v3);
    }
    for (; t < n; t++) {
        float4 v = tp[(size_t)s_cols[t] * T + tid];
        fma4(acc, s_w[t], v);
    }

    float di = g_dinv[row];
    float4 bv = ((const float4*)bias)[tid];
    float4 r;
    r.x = di * acc.x + bv.x;
    r.y = di * acc.y + bv.y;
    r.z = di * acc.z + bv.z;
    r.w = di * acc.w + bv.w;
    if (RELU) {
        r.x = fmaxf(r.x, 0.0f); r.y = fmaxf(r.y, 0.0f);
        r.z = fmaxf(r.z, 0.0f); r.w = fmaxf(r.w, 0.0f);
    }
    ((float4*)out)[(size_t)row * T + tid] = r;
}

// ===========================================================================
extern "C" void kernel_launch(void* const* d_in, const int* in_sizes, int n_in,
                              void* d_out, int out_size) {
    const float* x  = (const float*)d_in[0];
    const int*   ei = (const int*)d_in[1];
    const float* W1 = (const float*)d_in[2];
    const float* b1 = (const float*)d_in[3];
    const float* W2 = (const float*)d_in[4];
    const float* b2 = (const float*)d_in[5];
    const float* W3 = (const float*)d_in[6];
    const float* b3 = (const float*)d_in[7];
    float* out = (float*)d_out;

    int E = in_sizes[1] / 2;

    void *p0, *p1, *pa, *pb;
    cudaGetSymbolAddress(&p0, g_buf0);
    cudaGetSymbolAddress(&p1, g_buf1);
    cudaGetSymbolAddress(&pa, g_abf);
    cudaGetSymbolAddress(&pb, g_bbf);
    float* buf0 = (float*)p0;
    float* buf1 = (float*)p1;
    __nv_bfloat16* abf = (__nv_bfloat16*)pa;
    __nv_bfloat16* bbf = (__nv_bfloat16*)pb;

    // --- graph build ---
    k_clear_bits<<<NNODES * WORDS_PER_ROW / 256, 256>>>();
    k_detect<<<(E + 255) / 256, 256>>>(ei, 2 * E);
    k_scatter<<<(E + 255) / 256, 256>>>(ei, E);
    k_build_rows<<<NNODES / 8, 256>>>();

    dim3 g512(512 / 128, NNODES / 128);
    dim3 g256(256 / 128, NNODES / 128);
    int nA = NNODES * 512 / 256;

    // layer 1
    k_expandA<<<nA, 256>>>(x, abf);
    k_expandB<<<(512 * 512 + 255) / 256, 256>>>(W1, bbf, 512);
    k_gemm_mma<<<g512, 256>>>(abf, bbf, buf0, 512);
    k_spmm<512, true><<<NNODES, 128>>>(buf0, b1, buf1);

    // layer 2
    k_expandA<<<nA, 256>>>(buf1, abf);
    k_expandB<<<(512 * 512 + 255) / 256, 256>>>(W2, bbf, 512);
    k_gemm_mma<<<g512, 256>>>(abf, bbf, buf0, 512);
    k_spmm<512, true><<<NNODES, 128>>>(buf0, b2, buf1);

    // layer 3
    k_expandA<<<nA, 256>>>(buf1, abf);
    k_expandB<<<(256 * 512 + 255) / 256, 256>>>(W3, bbf, 256);
    k_gemm_mma<<<g256, 256>>>(abf, bbf, buf0, 256);
    k_spmm<256, false><<<NNODES, 64>>>(buf0, b3, out);
}